// round 4
// baseline (speedup 1.0000x reference)
#include <cuda_runtime.h>
#include <cstdint>

#define BB 128
#define PP 8732
#define NG (PP/4)      // 2183
#define MM 16
#define TPB 1024
#define NW (TPB/32)

__device__ float g_loc[BB];
__device__ float g_conf[BB];
__device__ int   g_npos[BB];
__device__ unsigned g_ctr = 0;

__device__ __forceinline__ unsigned midp(unsigned a, unsigned b) {
    return a + ((b - a + 1u) >> 1);   // candidate in [a+1, b] when b > a
}

__global__ __launch_bounds__(TPB, 1) void multibox_kernel(
    const float* __restrict__ locs,    // (B,P,4)
    const float* __restrict__ scores,  // (B,P,3)
    const float* __restrict__ boxes,   // (B,M,4) xyxy
    const int*   __restrict__ labels,  // (B,M)
    const float* __restrict__ priors,  // (P,4) cxcy
    float* __restrict__ out, int out_size)
{
    __shared__ __align__(16) float A[PP];          // sweep1: bint carry; later conf_neg
    __shared__ __align__(4)  unsigned char sobj[PP];
    __shared__ float4 sbox[MM];
    __shared__ float  sarea[MM];
    __shared__ float  bcx[MM], bcy[MM], bwd[MM], bht[MM];
    __shared__ int    blab[MM];
    __shared__ unsigned long long bestkey[MM];
    __shared__ float w_f0[NW], w_f1[NW];
    __shared__ int   w_i0[NW];
    __shared__ unsigned cnt[21];                   // 3 rotating sets x 7 counters
    __shared__ float s_conf, s_loc, s_sum;
    __shared__ int   s_np, s_last;
    __shared__ unsigned s_cnt;

    const int b    = blockIdx.x;
    const int tid  = threadIdx.x;
    const int warp = tid >> 5, lane = tid & 31;

    if (tid < MM) {
        float4 bb = *(const float4*)(boxes + ((size_t)b * MM + tid) * 4);
        sbox[tid] = bb;
        sarea[tid] = (bb.z - bb.x) * (bb.w - bb.y);
        bcx[tid] = (bb.x + bb.z) * 0.5f;
        bcy[tid] = (bb.y + bb.w) * 0.5f;
        bwd[tid] = bb.z - bb.x;
        bht[tid] = bb.w - bb.y;
        blab[tid] = labels[b * MM + tid];
        bestkey[tid] = 0ull;
    }
    if (tid < 21) cnt[tid] = 0u;
    __syncthreads();

    // ================= Phase 1, sweep 1: objects 0..7 =================
    {
        float oi[8], od[8]; int op[8];
#pragma unroll
        for (int m = 0; m < 8; m++) { oi[m] = 0.0f; od[m] = 1.0f; op[m] = 0; }

        for (int p = tid; p < PP; p += TPB) {
            float4 pr = *(const float4*)(priors + (size_t)p * 4);
            float hw = pr.z * 0.5f, hh = pr.w * 0.5f;
            float px1 = pr.x - hw, py1 = pr.y - hh, px2 = pr.x + hw, py2 = pr.y + hh;
            float parea = pr.z * pr.w;
            float bint = 0.0f, bden = 1.0f; int bm = 0;
#pragma unroll
            for (int m = 0; m < 8; m++) {
                float4 bb = sbox[m];
                float w = fminf(bb.z, px2) - fmaxf(bb.x, px1);
                float h = fminf(bb.w, py2) - fmaxf(bb.y, py1);
                w = fmaxf(w, 0.0f); h = fmaxf(h, 0.0f);
                float inter = w * h;
                float den = (sarea[m] + parea) - inter;
                if (inter * bden > bint * den) { bint = inter; bden = den; bm = m; }
                if (inter * od[m] > oi[m] * den) { oi[m] = inter; od[m] = den; op[m] = p; }
            }
            A[p] = bint;
            sobj[p] = (unsigned char)bm;
        }
        // per-object key reduce for m 0..7 (frees the tracker registers)
#pragma unroll
        for (int m = 0; m < 8; m++) {
            float iou = __fdividef(oi[m], od[m]);
            unsigned long long key =
                ((unsigned long long)__float_as_uint(iou) << 32) |
                (unsigned)(0xFFFFFFFFu - (unsigned)op[m]);
#pragma unroll
            for (int o = 16; o; o >>= 1) {
                unsigned long long other = __shfl_down_sync(0xFFFFFFFFu, key, o);
                if (other > key) key = other;
            }
            if (lane == 0) atomicMax(&bestkey[m], key);
        }
    }

    // ================= Phase 1, sweep 2: objects 8..15 =================
    {
        float oi[8], od[8]; int op[8];
#pragma unroll
        for (int m = 0; m < 8; m++) { oi[m] = 0.0f; od[m] = 1.0f; op[m] = 0; }

        for (int p = tid; p < PP; p += TPB) {
            float4 pr = *(const float4*)(priors + (size_t)p * 4);
            float hw = pr.z * 0.5f, hh = pr.w * 0.5f;
            float px1 = pr.x - hw, py1 = pr.y - hh, px2 = pr.x + hw, py2 = pr.y + hh;
            float parea = pr.z * pr.w;
            // reconstruct sweep-1 best (bit-exact: same expression, same operands)
            float bint = A[p];
            int   bm   = sobj[p];
            float bden = (sarea[bm] + parea) - bint;
#pragma unroll
            for (int m = 8; m < MM; m++) {
                float4 bb = sbox[m];
                float w = fminf(bb.z, px2) - fmaxf(bb.x, px1);
                float h = fminf(bb.w, py2) - fmaxf(bb.y, py1);
                w = fmaxf(w, 0.0f); h = fmaxf(h, 0.0f);
                float inter = w * h;
                float den = (sarea[m] + parea) - inter;
                if (inter * bden > bint * den) { bint = inter; bden = den; bm = m; }
                if (inter * od[m - 8] > oi[m - 8] * den) {
                    oi[m - 8] = inter; od[m - 8] = den; op[m - 8] = p;
                }
            }
            bool pos = (2.0f * bint >= bden);   // iou >= 0.5 (exact rational)
            sobj[p] = (unsigned char)(bm | (pos ? 0x80 : 0));
        }
#pragma unroll
        for (int m = 0; m < 8; m++) {
            float iou = __fdividef(oi[m], od[m]);
            unsigned long long key =
                ((unsigned long long)__float_as_uint(iou) << 32) |
                (unsigned)(0xFFFFFFFFu - (unsigned)op[m]);
#pragma unroll
            for (int o = 16; o; o >>= 1) {
                unsigned long long other = __shfl_down_sync(0xFFFFFFFFu, key, o);
                if (other > key) key = other;
            }
            if (lane == 0) atomicMax(&bestkey[m + 8], key);
        }
    }
    __syncthreads();

    // override: prior_obj[m] forced positive with object m (sequential, last wins)
    if (tid == 0) {
        for (int m = 0; m < MM; m++) {
            unsigned p = 0xFFFFFFFFu - (unsigned)(bestkey[m] & 0xFFFFFFFFull);
            sobj[p] = (unsigned char)(m | 0x80);
        }
    }
    __syncthreads();

    // ================= Phase 3: BCE + loc-loss, conf_neg into A =================
    float conf_pos = 0.0f, loc_sum = 0.0f;
    int npos = 0;
    const float* srow = scores + (size_t)b * PP * 3;
    for (int g = tid; g < NG; g += TPB) {
        const float4* sp = (const float4*)srow + (size_t)g * 3;
        float4 s0 = sp[0], s1 = sp[1], s2 = sp[2];
        unsigned ob4 = ((const unsigned*)sobj)[g];
        float ch0[4] = { s0.x, s0.w, s1.z, s2.y };
        float ch1[4] = { s0.y, s1.x, s1.w, s2.z };
        float ch2[4] = { s0.z, s1.y, s2.x, s2.w };
        float v[4];
#pragma unroll
        for (int j = 0; j < 4; j++) {
            unsigned obf = (ob4 >> (8 * j)) & 0xFFu;
            int obj = (int)(obf & 0x7Fu);
            bool pos = (obf & 0x80u) != 0;
            float x0 = ch0[j], x1 = ch1[j], x2 = ch2[j];
            float bce = fmaxf(x0, 0.0f) + __logf(1.0f + __expf(-fabsf(x0)))
                      + fmaxf(x1, 0.0f) + __logf(1.0f + __expf(-fabsf(x1)))
                      + fmaxf(x2, 0.0f) + __logf(1.0f + __expf(-fabsf(x2)));
            int lab = pos ? blab[obj] : 0;
            if (lab == 0) bce -= x0;
            if (lab == 1 || lab == 3) bce -= x1;
            if (lab >= 2) bce -= x2;
            if (pos) {
                conf_pos += bce;
                npos++;
                v[j] = 0.0f;
                int p = 4 * g + j;
                float4 pr = *(const float4*)(priors + (size_t)p * 4);
                float gx = (bcx[obj] - pr.x) * 10.0f * __fdividef(1.0f, pr.z);
                float gy = (bcy[obj] - pr.y) * 10.0f * __fdividef(1.0f, pr.w);
                float gw = __logf(__fdividef(bwd[obj], pr.z)) * 5.0f;
                float gh = __logf(__fdividef(bht[obj], pr.w)) * 5.0f;
                float4 pl = *(const float4*)(locs + ((size_t)b * PP + p) * 4);
                loc_sum += fabsf(pl.x - gx) + fabsf(pl.y - gy) +
                           fabsf(pl.z - gw) + fabsf(pl.w - gh);
            } else {
                v[j] = bce;
            }
        }
        ((float4*)A)[g] = make_float4(v[0], v[1], v[2], v[3]);
    }

    // ---- deterministic block reduce ----
#pragma unroll
    for (int o = 16; o; o >>= 1) {
        conf_pos += __shfl_down_sync(0xFFFFFFFFu, conf_pos, o);
        loc_sum  += __shfl_down_sync(0xFFFFFFFFu, loc_sum, o);
    }
    npos = __reduce_add_sync(0xFFFFFFFFu, npos);
    if (lane == 0) { w_f0[warp] = conf_pos; w_f1[warp] = loc_sum; w_i0[warp] = npos; }
    __syncthreads();
    if (tid == 0) {
        float c = 0.0f, l = 0.0f; int n = 0;
#pragma unroll
        for (int i = 0; i < NW; i++) { c += w_f0[i]; l += w_f1[i]; n += w_i0[i]; }
        s_conf = c; s_loc = l; s_np = n;
    }
    __syncthreads();

    const int npos_b = s_np;
    const unsigned K = 3u * (unsigned)npos_b;

    // ========== Phase 4: top-K sum via 8-way (3 bits/round) bisection ==========
    float hard = 0.0f;
    if (K > 0) {
        unsigned lo = 0u, hi = 0x7F800000u;
        int r = 0;
        const float4* sv4 = (const float4*)A;
        while (lo < hi) {
            // 7 candidate thresholds = 3 levels of midpoint recursion
            unsigned t1  = midp(lo, hi);
            unsigned t2a = midp(lo, t1 - 1u);
            unsigned t2b = midp(t1, hi);
            unsigned t3a = midp(lo, t2a - 1u);
            unsigned t3b = midp(t2a, t1 - 1u);
            unsigned t3c = midp(t1, t2b - 1u);
            unsigned t3d = midp(t2b, hi);
            unsigned T[7] = { t3a, t2a, t3b, t1, t3c, t2b, t3d };
            int n[7] = {0, 0, 0, 0, 0, 0, 0};
            for (int g = tid; g < NG; g += TPB) {
                float4 vv = sv4[g];
                unsigned u0 = __float_as_uint(vv.x), u1 = __float_as_uint(vv.y);
                unsigned u2 = __float_as_uint(vv.z), u3 = __float_as_uint(vv.w);
#pragma unroll
                for (int i = 0; i < 7; i++)
                    n[i] += (u0 >= T[i]) + (u1 >= T[i]) + (u2 >= T[i]) + (u3 >= T[i]);
            }
            int s = (r % 3) * 7;
#pragma unroll
            for (int i = 0; i < 7; i++) {
                n[i] = __reduce_add_sync(0xFFFFFFFFu, n[i]);
                if (lane == 0 && n[i]) atomicAdd(&cnt[s + i], (unsigned)n[i]);
            }
            if (tid == 0) {
                int z = ((r + 1) % 3) * 7;
#pragma unroll
                for (int i = 0; i < 7; i++) cnt[z + i] = 0u;
            }
            __syncthreads();
            unsigned C3a = cnt[s+0], C2a = cnt[s+1], C3b = cnt[s+2], C1 = cnt[s+3];
            unsigned C3c = cnt[s+4], C2b = cnt[s+5], C3d = cnt[s+6];
            // 3 binary steps using precomputed counts
            if (C1 >= K) {
                lo = t1;
                if (lo < hi) {
                    if (C2b >= K) { lo = t2b;
                        if (lo < hi) { if (C3d >= K) lo = t3d; else hi = t3d - 1u; } }
                    else { hi = t2b - 1u;
                        if (lo < hi) { if (C3c >= K) lo = t3c; else hi = t3c - 1u; } }
                }
            } else {
                hi = t1 - 1u;
                if (lo < hi) {
                    if (C2a >= K) { lo = t2a;
                        if (lo < hi) { if (C3b >= K) lo = t3b; else hi = t3b - 1u; } }
                    else { hi = t2a - 1u;
                        if (lo < hi) { if (C3a >= K) lo = t3a; else hi = t3a - 1u; } }
                }
            }
            r++;
        }
        const float thr = __uint_as_float(lo);
        if (tid == 0) s_cnt = 0u;
        __syncthreads();
        int c = 0; float ssum = 0.0f;
        for (int g = tid; g < NG; g += TPB) {
            float4 vv = sv4[g];
            if (vv.x > thr) { c++; ssum += vv.x; }
            if (vv.y > thr) { c++; ssum += vv.y; }
            if (vv.z > thr) { c++; ssum += vv.z; }
            if (vv.w > thr) { c++; ssum += vv.w; }
        }
#pragma unroll
        for (int o = 16; o; o >>= 1)
            ssum += __shfl_down_sync(0xFFFFFFFFu, ssum, o);
        c = __reduce_add_sync(0xFFFFFFFFu, c);
        if (lane == 0) { w_f0[warp] = ssum; atomicAdd(&s_cnt, (unsigned)c); }
        __syncthreads();
        if (tid == 0) {
            float t = 0.0f;
#pragma unroll
            for (int i = 0; i < NW; i++) t += w_f0[i];
            s_sum = t + (float)((int)K - (int)s_cnt) * thr;
        }
        __syncthreads();
        hard = s_sum;
    }

    // ---- per-row results + last-CTA fused finalize ----
    if (tid == 0) {
        g_conf[b] = s_conf + hard;
        g_loc[b]  = s_loc;
        g_npos[b] = npos_b;
        __threadfence();
        unsigned v = atomicAdd(&g_ctr, 1u);
        s_last = (v == (unsigned)(BB - 1));
    }
    __syncthreads();

    if (s_last) {
        __threadfence();
        float l = 0.0f, c = 0.0f; int n = 0;
        if (tid < BB) { l = g_loc[tid]; c = g_conf[tid]; n = g_npos[tid]; }
#pragma unroll
        for (int o = 16; o; o >>= 1) {
            l += __shfl_down_sync(0xFFFFFFFFu, l, o);
            c += __shfl_down_sync(0xFFFFFFFFu, c, o);
        }
        n = __reduce_add_sync(0xFFFFFFFFu, n);
        if (lane == 0) { w_f0[warp] = l; w_f1[warp] = c; w_i0[warp] = n; }
        __syncthreads();
        if (tid == 0) {
            float locsum = 0.0f, confsum = 0.0f; long long np = 0;
#pragma unroll
            for (int i = 0; i < 4; i++) {   // rows live in warps 0-3 only
                locsum += w_f0[i]; confsum += w_f1[i]; np += w_i0[i];
            }
            float npf = (float)np;
            float loc_loss  = (np > 0) ? locsum / (4.0f * fmaxf(npf, 1.0f)) : 0.0f;
            float conf_loss = confsum / (1e-10f + npf);
            float total = conf_loss + loc_loss;
            if (out_size > 0) out[0] = total;
            if (out_size > 1) out[1] = conf_loss;
            if (out_size > 2) out[2] = loc_loss;
            g_ctr = 0u;    // reset for next graph replay
        }
        if (tid < BB && 3 + tid < out_size) out[3 + tid] = (float)g_npos[tid];
        for (int i = 3 + BB + tid; i < out_size; i += TPB) out[i] = 0.0f;
    }
}

extern "C" void kernel_launch(void* const* d_in, const int* in_sizes, int n_in,
                              void* d_out, int out_size) {
    const float* locs   = (const float*)d_in[0];   // (128,8732,4) f32
    const float* scores = (const float*)d_in[1];   // (128,8732,3) f32
    const float* boxes  = (const float*)d_in[2];   // (128,16,4)   f32
    const int*   labels = (const int*)d_in[3];     // (128,16)     i32
    const float* priors = (const float*)d_in[4];   // (8732,4)     f32

    multibox_kernel<<<BB, TPB>>>(locs, scores, boxes, labels, priors,
                                 (float*)d_out, out_size);
}

// round 6
// speedup vs baseline: 1.0323x; 1.0323x over previous
#include <cuda_runtime.h>
#include <cstdint>

#define BB 128
#define PP 8732
#define NG (PP/4)      // 2183
#define MM 16
#define TPB 512
#define NW (TPB/32)

__device__ float g_loc[BB];
__device__ float g_conf[BB];
__device__ int   g_npos[BB];
__device__ unsigned g_ctr = 0;

__device__ __forceinline__ unsigned midp(unsigned a, unsigned b) {
    return a + ((b - a + 1u) >> 1);   // candidate in [a+1, b] when b > a
}

__global__ __launch_bounds__(TPB, 1) void multibox_kernel(
    const float* __restrict__ locs,    // (B,P,4)
    const float* __restrict__ scores,  // (B,P,3)
    const float* __restrict__ boxes,   // (B,M,4) xyxy
    const int*   __restrict__ labels,  // (B,M)
    const float* __restrict__ priors,  // (P,4) cxcy
    float* __restrict__ out, int out_size)
{
    __shared__ __align__(16) float A[PP];            // conf_neg per prior
    __shared__ __align__(4)  unsigned char sobj[PP]; // obj | 0x80 positive flag
    __shared__ float4 sbox[MM];
    __shared__ float  sarea[MM];
    __shared__ float  bcx[MM], bcy[MM], bwd[MM], bht[MM];
    __shared__ int    blab[MM];
    __shared__ unsigned long long bestkey[MM];
    __shared__ float w_f0[NW], w_f1[NW];
    __shared__ int   w_i0[NW];
    __shared__ unsigned cnt[21];                     // 3 rotating sets x 7 counters
    __shared__ float s_conf, s_loc, s_sum;
    __shared__ int   s_np, s_last;
    __shared__ unsigned s_cnt;

    const int b    = blockIdx.x;
    const int tid  = threadIdx.x;
    const int warp = tid >> 5, lane = tid & 31;

    if (tid < MM) {
        float4 bb = *(const float4*)(boxes + ((size_t)b * MM + tid) * 4);
        sbox[tid] = bb;
        sarea[tid] = (bb.z - bb.x) * (bb.w - bb.y);
        bcx[tid] = (bb.x + bb.z) * 0.5f;
        bcy[tid] = (bb.y + bb.w) * 0.5f;
        bwd[tid] = bb.z - bb.x;
        bht[tid] = bb.w - bb.y;
        blab[tid] = labels[b * MM + tid];
        bestkey[tid] = 0ull;
    }
    if (tid < 21) cnt[tid] = 0u;
    __syncthreads();

    // ===== Phase 1: single sweep, division-free (exact rational compares) =====
    // iou = inter/(S - inter), S = sarea[m] + parea.
    // iou1 > iou2  <=>  inter1*S2 > inter2*S1  (cross terms cancel exactly).
    {
        float oi[MM], oS[MM]; int op[MM];
#pragma unroll
        for (int m = 0; m < MM; m++) { oi[m] = 0.0f; oS[m] = 1.0f; op[m] = 0; }

        for (int p = tid; p < PP; p += TPB) {
            float4 pr = *(const float4*)(priors + (size_t)p * 4);
            float hw = pr.z * 0.5f, hh = pr.w * 0.5f;
            float px1 = pr.x - hw, py1 = pr.y - hh, px2 = pr.x + hw, py2 = pr.y + hh;
            float parea = pr.z * pr.w;
            float bint = 0.0f, bS = 1.0f; int bm = 0;
#pragma unroll
            for (int m = 0; m < MM; m++) {
                float4 bb = sbox[m];
                float w = fminf(bb.z, px2) - fmaxf(bb.x, px1);
                float h = fminf(bb.w, py2) - fmaxf(bb.y, py1);
                float inter = fmaxf(w, 0.0f) * fmaxf(h, 0.0f);
                float S = sarea[m] + parea;
                // per-prior argmax over m
                if (inter * bS > bint * S) { bint = inter; bS = S; bm = m; }
                // per-object argmax over p (exact: cross-multiplied)
                if (inter * oS[m] > oi[m] * S) { oi[m] = inter; oS[m] = S; op[m] = p; }
            }
            bool pos = (3.0f * bint >= bS);            // iou >= 0.5 exactly
            sobj[p] = (unsigned char)(bm | (pos ? 0x80 : 0));
        }
        // cross-thread per-object argmax: key = (iou_bits, ~p)
#pragma unroll
        for (int m = 0; m < MM; m++) {
            float iou = __fdividef(oi[m], oS[m] - oi[m]);
            unsigned long long key =
                ((unsigned long long)__float_as_uint(iou) << 32) |
                (unsigned)(0xFFFFFFFFu - (unsigned)op[m]);
#pragma unroll
            for (int o = 16; o; o >>= 1) {
                unsigned long long other = __shfl_down_sync(0xFFFFFFFFu, key, o);
                if (other > key) key = other;
            }
            if (lane == 0) atomicMax(&bestkey[m], key);
        }
    }
    __syncthreads();

    // override: prior_obj[m] forced positive with object m (sequential, last wins)
    if (tid == 0) {
        for (int m = 0; m < MM; m++) {
            unsigned p = 0xFFFFFFFFu - (unsigned)(bestkey[m] & 0xFFFFFFFFull);
            sobj[p] = (unsigned char)(m | 0x80);
        }
    }
    __syncthreads();

    // ===== Phase 3: BCE + loc-loss, conf_neg into A =====
    float conf_pos = 0.0f, loc_sum = 0.0f;
    int npos = 0;
    const float* srow = scores + (size_t)b * PP * 3;
    for (int g = tid; g < NG; g += TPB) {
        const float4* sp = (const float4*)srow + (size_t)g * 3;
        float4 s0 = sp[0], s1 = sp[1], s2 = sp[2];
        unsigned ob4 = ((const unsigned*)sobj)[g];
        float ch0[4] = { s0.x, s0.w, s1.z, s2.y };
        float ch1[4] = { s0.y, s1.x, s1.w, s2.z };
        float ch2[4] = { s0.z, s1.y, s2.x, s2.w };
        float v[4];
#pragma unroll
        for (int j = 0; j < 4; j++) {
            unsigned obf = (ob4 >> (8 * j)) & 0xFFu;
            int obj = (int)(obf & 0x7Fu);
            bool pos = (obf & 0x80u) != 0;
            float x0 = ch0[j], x1 = ch1[j], x2 = ch2[j];
            float bce = fmaxf(x0, 0.0f) + __logf(1.0f + __expf(-fabsf(x0)))
                      + fmaxf(x1, 0.0f) + __logf(1.0f + __expf(-fabsf(x1)))
                      + fmaxf(x2, 0.0f) + __logf(1.0f + __expf(-fabsf(x2)));
            int lab = pos ? blab[obj] : 0;
            if (lab == 0) bce -= x0;
            if (lab == 1 || lab == 3) bce -= x1;
            if (lab >= 2) bce -= x2;
            if (pos) {
                conf_pos += bce;
                npos++;
                v[j] = 0.0f;
                int p = 4 * g + j;
                float4 pr = *(const float4*)(priors + (size_t)p * 4);
                float gx = (bcx[obj] - pr.x) * 10.0f * __fdividef(1.0f, pr.z);
                float gy = (bcy[obj] - pr.y) * 10.0f * __fdividef(1.0f, pr.w);
                float gw = __logf(__fdividef(bwd[obj], pr.z)) * 5.0f;
                float gh = __logf(__fdividef(bht[obj], pr.w)) * 5.0f;
                float4 pl = *(const float4*)(locs + ((size_t)b * PP + p) * 4);
                loc_sum += fabsf(pl.x - gx) + fabsf(pl.y - gy) +
                           fabsf(pl.z - gw) + fabsf(pl.w - gh);
            } else {
                v[j] = bce;
            }
        }
        ((float4*)A)[g] = make_float4(v[0], v[1], v[2], v[3]);
    }

    // ---- deterministic block reduce ----
#pragma unroll
    for (int o = 16; o; o >>= 1) {
        conf_pos += __shfl_down_sync(0xFFFFFFFFu, conf_pos, o);
        loc_sum  += __shfl_down_sync(0xFFFFFFFFu, loc_sum, o);
    }
    npos = __reduce_add_sync(0xFFFFFFFFu, npos);
    if (lane == 0) { w_f0[warp] = conf_pos; w_f1[warp] = loc_sum; w_i0[warp] = npos; }
    __syncthreads();
    if (tid == 0) {
        float c = 0.0f, l = 0.0f; int n = 0;
#pragma unroll
        for (int i = 0; i < NW; i++) { c += w_f0[i]; l += w_f1[i]; n += w_i0[i]; }
        s_conf = c; s_loc = l; s_np = n;
    }
    __syncthreads();

    const int npos_b = s_np;
    const unsigned K = 3u * (unsigned)npos_b;

    // ===== Phase 4: top-K sum via 8-way (3 bits/round) bisection =====
    float hard = 0.0f;
    if (K > 0) {
        unsigned lo = 0u, hi = 0x7F800000u;
        int r = 0;
        const float4* sv4 = (const float4*)A;
        while (lo < hi) {
            unsigned t1  = midp(lo, hi);
            unsigned t2a = midp(lo, t1 - 1u);
            unsigned t2b = midp(t1, hi);
            unsigned t3a = midp(lo, t2a - 1u);
            unsigned t3b = midp(t2a, t1 - 1u);
            unsigned t3c = midp(t1, t2b - 1u);
            unsigned t3d = midp(t2b, hi);
            unsigned T[7] = { t3a, t2a, t3b, t1, t3c, t2b, t3d };
            int n[7] = {0, 0, 0, 0, 0, 0, 0};
            for (int g = tid; g < NG; g += TPB) {
                float4 vv = sv4[g];
                unsigned u0 = __float_as_uint(vv.x), u1 = __float_as_uint(vv.y);
                unsigned u2 = __float_as_uint(vv.z), u3 = __float_as_uint(vv.w);
#pragma unroll
                for (int i = 0; i < 7; i++)
                    n[i] += (u0 >= T[i]) + (u1 >= T[i]) + (u2 >= T[i]) + (u3 >= T[i]);
            }
            int s = (r % 3) * 7;
#pragma unroll
            for (int i = 0; i < 7; i++) {
                n[i] = __reduce_add_sync(0xFFFFFFFFu, n[i]);
                if (lane == 0 && n[i]) atomicAdd(&cnt[s + i], (unsigned)n[i]);
            }
            if (tid == 0) {
                int z = ((r + 1) % 3) * 7;
#pragma unroll
                for (int i = 0; i < 7; i++) cnt[z + i] = 0u;
            }
            __syncthreads();
            unsigned C3a = cnt[s+0], C2a = cnt[s+1], C3b = cnt[s+2], C1 = cnt[s+3];
            unsigned C3c = cnt[s+4], C2b = cnt[s+5], C3d = cnt[s+6];
            if (C1 >= K) {
                lo = t1;
                if (lo < hi) {
                    if (C2b >= K) { lo = t2b;
                        if (lo < hi) { if (C3d >= K) lo = t3d; else hi = t3d - 1u; } }
                    else { hi = t2b - 1u;
                        if (lo < hi) { if (C3c >= K) lo = t3c; else hi = t3c - 1u; } }
                }
            } else {
                hi = t1 - 1u;
                if (lo < hi) {
                    if (C2a >= K) { lo = t2a;
                        if (lo < hi) { if (C3b >= K) lo = t3b; else hi = t3b - 1u; } }
                    else { hi = t2a - 1u;
                        if (lo < hi) { if (C3a >= K) lo = t3a; else hi = t3a - 1u; } }
                }
            }
            r++;
        }
        const float thr = __uint_as_float(lo);
        if (tid == 0) s_cnt = 0u;
        __syncthreads();
        int c = 0; float ssum = 0.0f;
        for (int g = tid; g < NG; g += TPB) {
            float4 vv = sv4[g];
            if (vv.x > thr) { c++; ssum += vv.x; }
            if (vv.y > thr) { c++; ssum += vv.y; }
            if (vv.z > thr) { c++; ssum += vv.z; }
            if (vv.w > thr) { c++; ssum += vv.w; }
        }
#pragma unroll
        for (int o = 16; o; o >>= 1)
            ssum += __shfl_down_sync(0xFFFFFFFFu, ssum, o);
        c = __reduce_add_sync(0xFFFFFFFFu, c);
        if (lane == 0) { w_f0[warp] = ssum; atomicAdd(&s_cnt, (unsigned)c); }
        __syncthreads();
        if (tid == 0) {
            float t = 0.0f;
#pragma unroll
            for (int i = 0; i < NW; i++) t += w_f0[i];
            s_sum = t + (float)((int)K - (int)s_cnt) * thr;
        }
        __syncthreads();
        hard = s_sum;
    }

    // ---- per-row results + last-CTA fused finalize ----
    if (tid == 0) {
        g_conf[b] = s_conf + hard;
        g_loc[b]  = s_loc;
        g_npos[b] = npos_b;
        __threadfence();
        unsigned v = atomicAdd(&g_ctr, 1u);
        s_last = (v == (unsigned)(BB - 1));
    }
    __syncthreads();

    if (s_last) {
        __threadfence();
        float l = 0.0f, c = 0.0f; int n = 0;
        if (tid < BB) { l = g_loc[tid]; c = g_conf[tid]; n = g_npos[tid]; }
#pragma unroll
        for (int o = 16; o; o >>= 1) {
            l += __shfl_down_sync(0xFFFFFFFFu, l, o);
            c += __shfl_down_sync(0xFFFFFFFFu, c, o);
        }
        n = __reduce_add_sync(0xFFFFFFFFu, n);
        if (lane == 0) { w_f0[warp] = l; w_f1[warp] = c; w_i0[warp] = n; }
        __syncthreads();
        if (tid == 0) {
            float locsum = 0.0f, confsum = 0.0f; long long np = 0;
#pragma unroll
            for (int i = 0; i < 4; i++) {   // rows live in warps 0-3 only
                locsum += w_f0[i]; confsum += w_f1[i]; np += w_i0[i];
            }
            float npf = (float)np;
            float loc_loss  = (np > 0) ? locsum / (4.0f * fmaxf(npf, 1.0f)) : 0.0f;
            float conf_loss = confsum / (1e-10f + npf);
            float total = conf_loss + loc_loss;
            if (out_size > 0) out[0] = total;
            if (out_size > 1) out[1] = conf_loss;
            if (out_size > 2) out[2] = loc_loss;
            g_ctr = 0u;    // reset for next graph replay
        }
        if (tid < BB && 3 + tid < out_size) out[3 + tid] = (float)g_npos[tid];
        for (int i = 3 + BB + tid; i < out_size; i += TPB) out[i] = 0.0f;
    }
}

extern "C" void kernel_launch(void* const* d_in, const int* in_sizes, int n_in,
                              void* d_out, int out_size) {
    const float* locs   = (const float*)d_in[0];   // (128,8732,4) f32
    const float* scores = (const float*)d_in[1];   // (128,8732,3) f32
    const float* boxes  = (const float*)d_in[2];   // (128,16,4)   f32
    const int*   labels = (const int*)d_in[3];     // (128,16)     i32
    const float* priors = (const float*)d_in[4];   // (8732,4)     f32

    multibox_kernel<<<BB, TPB>>>(locs, scores, boxes, labels, priors,
                                 (float*)d_out, out_size);
}

// round 7
// speedup vs baseline: 1.1802x; 1.1434x over previous
#include <cuda_runtime.h>
#include <cstdint>

#define BB 128
#define PP 8732
#define NG (PP/4)      // 2183
#define MM 16
#define TPB 512
#define NW (TPB/32)

__device__ float g_loc[BB];
__device__ float g_conf[BB];
__device__ int   g_npos[BB];
__device__ unsigned g_ctr = 0;

__device__ __forceinline__ unsigned midp(unsigned a, unsigned b) {
    return a + ((b - a + 1u) >> 1);   // candidate in [a+1, b] when b > a
}

__global__ __launch_bounds__(TPB, 1) void multibox_kernel(
    const float* __restrict__ locs,    // (B,P,4)
    const float* __restrict__ scores,  // (B,P,3)
    const float* __restrict__ boxes,   // (B,M,4) xyxy
    const int*   __restrict__ labels,  // (B,M)
    const float* __restrict__ priors,  // (P,4) cxcy
    float* __restrict__ out, int out_size)
{
    __shared__ __align__(16) float A[PP];            // conf_neg per prior
    __shared__ __align__(4)  unsigned char sobj[PP]; // obj | 0x80 positive flag
    __shared__ float4 sbox[MM];
    __shared__ float  sarea[MM];
    __shared__ float  bcx[MM], bcy[MM], bwd[MM], bht[MM];
    __shared__ int    blab[MM];
    __shared__ unsigned long long bestkey[MM];
    __shared__ float w_f0[NW], w_f1[NW];
    __shared__ int   w_i0[NW];
    __shared__ unsigned cnt[9];                      // 3 rotating sets x 3 counters
    __shared__ float s_conf, s_loc, s_sum;
    __shared__ int   s_np, s_last;
    __shared__ unsigned s_cnt;

    const int b    = blockIdx.x;
    const int tid  = threadIdx.x;
    const int warp = tid >> 5, lane = tid & 31;

    if (tid < MM) {
        float4 bb = *(const float4*)(boxes + ((size_t)b * MM + tid) * 4);
        sbox[tid] = bb;
        sarea[tid] = (bb.z - bb.x) * (bb.w - bb.y);
        bcx[tid] = (bb.x + bb.z) * 0.5f;
        bcy[tid] = (bb.y + bb.w) * 0.5f;
        bwd[tid] = bb.z - bb.x;
        bht[tid] = bb.w - bb.y;
        blab[tid] = labels[b * MM + tid];
        bestkey[tid] = 0ull;
    }
    if (tid < 9) cnt[tid] = 0u;
    __syncthreads();

    // ===== Phase 1: single sweep, division-free (exact rational compares) =====
    // iou = inter/(S - inter), S = sarea[m] + parea.
    // iou1 > iou2  <=>  inter1*S2 > inter2*S1  (cross terms cancel exactly).
    {
        float oi[MM], oS[MM]; int op[MM];
#pragma unroll
        for (int m = 0; m < MM; m++) { oi[m] = 0.0f; oS[m] = 1.0f; op[m] = 0; }

        for (int p = tid; p < PP; p += TPB) {
            float4 pr = *(const float4*)(priors + (size_t)p * 4);
            float hw = pr.z * 0.5f, hh = pr.w * 0.5f;
            float px1 = pr.x - hw, py1 = pr.y - hh, px2 = pr.x + hw, py2 = pr.y + hh;
            float parea = pr.z * pr.w;
            float bint = 0.0f, bS = 1.0f; int bm = 0;
#pragma unroll
            for (int m = 0; m < MM; m++) {
                float4 bb = sbox[m];
                float w = fminf(bb.z, px2) - fmaxf(bb.x, px1);
                float h = fminf(bb.w, py2) - fmaxf(bb.y, py1);
                float inter = fmaxf(w, 0.0f) * fmaxf(h, 0.0f);
                float S = sarea[m] + parea;
                // per-prior argmax over m
                if (inter * bS > bint * S) { bint = inter; bS = S; bm = m; }
                // per-object argmax over p (exact: cross-multiplied)
                if (inter * oS[m] > oi[m] * S) { oi[m] = inter; oS[m] = S; op[m] = p; }
            }
            bool pos = (3.0f * bint >= bS);            // iou >= 0.5 exactly
            sobj[p] = (unsigned char)(bm | (pos ? 0x80 : 0));
        }
        // cross-thread per-object argmax: key = (iou_bits, ~p)
#pragma unroll
        for (int m = 0; m < MM; m++) {
            float iou = __fdividef(oi[m], oS[m] - oi[m]);
            unsigned long long key =
                ((unsigned long long)__float_as_uint(iou) << 32) |
                (unsigned)(0xFFFFFFFFu - (unsigned)op[m]);
#pragma unroll
            for (int o = 16; o; o >>= 1) {
                unsigned long long other = __shfl_down_sync(0xFFFFFFFFu, key, o);
                if (other > key) key = other;
            }
            if (lane == 0) atomicMax(&bestkey[m], key);
        }
    }
    __syncthreads();

    // override: prior_obj[m] forced positive with object m (sequential, last wins)
    if (tid == 0) {
        for (int m = 0; m < MM; m++) {
            unsigned p = 0xFFFFFFFFu - (unsigned)(bestkey[m] & 0xFFFFFFFFull);
            sobj[p] = (unsigned char)(m | 0x80);
        }
    }
    __syncthreads();

    // ===== Phase 3: BCE + loc-loss, conf_neg into A =====
    float conf_pos = 0.0f, loc_sum = 0.0f;
    int npos = 0;
    const float* srow = scores + (size_t)b * PP * 3;
    for (int g = tid; g < NG; g += TPB) {
        const float4* sp = (const float4*)srow + (size_t)g * 3;
        float4 s0 = sp[0], s1 = sp[1], s2 = sp[2];
        unsigned ob4 = ((const unsigned*)sobj)[g];
        float ch0[4] = { s0.x, s0.w, s1.z, s2.y };
        float ch1[4] = { s0.y, s1.x, s1.w, s2.z };
        float ch2[4] = { s0.z, s1.y, s2.x, s2.w };
        float v[4];
#pragma unroll
        for (int j = 0; j < 4; j++) {
            unsigned obf = (ob4 >> (8 * j)) & 0xFFu;
            int obj = (int)(obf & 0x7Fu);
            bool pos = (obf & 0x80u) != 0;
            float x0 = ch0[j], x1 = ch1[j], x2 = ch2[j];
            float bce = fmaxf(x0, 0.0f) + __logf(1.0f + __expf(-fabsf(x0)))
                      + fmaxf(x1, 0.0f) + __logf(1.0f + __expf(-fabsf(x1)))
                      + fmaxf(x2, 0.0f) + __logf(1.0f + __expf(-fabsf(x2)));
            int lab = pos ? blab[obj] : 0;
            if (lab == 0) bce -= x0;
            if (lab == 1 || lab == 3) bce -= x1;
            if (lab >= 2) bce -= x2;
            if (pos) {
                conf_pos += bce;
                npos++;
                v[j] = 0.0f;
                int p = 4 * g + j;
                float4 pr = *(const float4*)(priors + (size_t)p * 4);
                float gx = (bcx[obj] - pr.x) * 10.0f * __fdividef(1.0f, pr.z);
                float gy = (bcy[obj] - pr.y) * 10.0f * __fdividef(1.0f, pr.w);
                float gw = __logf(__fdividef(bwd[obj], pr.z)) * 5.0f;
                float gh = __logf(__fdividef(bht[obj], pr.w)) * 5.0f;
                float4 pl = *(const float4*)(locs + ((size_t)b * PP + p) * 4);
                loc_sum += fabsf(pl.x - gx) + fabsf(pl.y - gy) +
                           fabsf(pl.z - gw) + fabsf(pl.w - gh);
            } else {
                v[j] = bce;
            }
        }
        ((float4*)A)[g] = make_float4(v[0], v[1], v[2], v[3]);
    }

    // ---- deterministic block reduce ----
#pragma unroll
    for (int o = 16; o; o >>= 1) {
        conf_pos += __shfl_down_sync(0xFFFFFFFFu, conf_pos, o);
        loc_sum  += __shfl_down_sync(0xFFFFFFFFu, loc_sum, o);
    }
    npos = __reduce_add_sync(0xFFFFFFFFu, npos);
    if (lane == 0) { w_f0[warp] = conf_pos; w_f1[warp] = loc_sum; w_i0[warp] = npos; }
    __syncthreads();
    if (tid == 0) {
        float c = 0.0f, l = 0.0f; int n = 0;
#pragma unroll
        for (int i = 0; i < NW; i++) { c += w_f0[i]; l += w_f1[i]; n += w_i0[i]; }
        s_conf = c; s_loc = l; s_np = n;
    }
    __syncthreads();

    const int npos_b = s_np;
    const unsigned K = 3u * (unsigned)npos_b;

    // ===== Phase 4: top-K sum via 4-way (2 bits/round) bisection =====
    float hard = 0.0f;
    if (K > 0) {
        unsigned lo = 0u, hi = 0x7F800000u;
        int r = 0;
        const float4* sv4 = (const float4*)A;
        while (lo < hi) {
            unsigned c2v = midp(lo, hi);                 // in [lo+1, hi]
            unsigned c1v = lo + ((c2v - lo) >> 1);       // used if c2v-1 > lo
            unsigned c3v = midp(c2v, hi);                // used if hi > c2v
            int n1 = 0, n2 = 0, n3 = 0;
            for (int g = tid; g < NG; g += TPB) {
                float4 vv = sv4[g];
                unsigned u0 = __float_as_uint(vv.x), u1 = __float_as_uint(vv.y);
                unsigned u2 = __float_as_uint(vv.z), u3 = __float_as_uint(vv.w);
                n1 += (u0 >= c1v) + (u1 >= c1v) + (u2 >= c1v) + (u3 >= c1v);
                n2 += (u0 >= c2v) + (u1 >= c2v) + (u2 >= c2v) + (u3 >= c2v);
                n3 += (u0 >= c3v) + (u1 >= c3v) + (u2 >= c3v) + (u3 >= c3v);
            }
            n1 = __reduce_add_sync(0xFFFFFFFFu, n1);
            n2 = __reduce_add_sync(0xFFFFFFFFu, n2);
            n3 = __reduce_add_sync(0xFFFFFFFFu, n3);
            int s = (r % 3) * 3;
            if (lane == 0)      atomicAdd(&cnt[s + 0], (unsigned)n1);
            else if (lane == 1) atomicAdd(&cnt[s + 1], (unsigned)n2);
            else if (lane == 2) atomicAdd(&cnt[s + 2], (unsigned)n3);
            if (tid == 0) {
                int z = ((r + 1) % 3) * 3;
                cnt[z + 0] = 0u; cnt[z + 1] = 0u; cnt[z + 2] = 0u;
            }
            __syncthreads();
            unsigned N1 = cnt[s + 0], N2 = cnt[s + 1], N3 = cnt[s + 2];
            if (N2 >= K) {
                lo = c2v;
                if (hi > lo) { if (N3 >= K) lo = c3v; else hi = c3v - 1u; }
            } else {
                hi = c2v - 1u;
                if (hi > lo) { if (N1 >= K) lo = c1v; else hi = c1v - 1u; }
            }
            r++;
        }
        const float thr = __uint_as_float(lo);
        if (tid == 0) s_cnt = 0u;
        __syncthreads();
        int c = 0; float ssum = 0.0f;
        for (int g = tid; g < NG; g += TPB) {
            float4 vv = sv4[g];
            if (vv.x > thr) { c++; ssum += vv.x; }
            if (vv.y > thr) { c++; ssum += vv.y; }
            if (vv.z > thr) { c++; ssum += vv.z; }
            if (vv.w > thr) { c++; ssum += vv.w; }
        }
#pragma unroll
        for (int o = 16; o; o >>= 1)
            ssum += __shfl_down_sync(0xFFFFFFFFu, ssum, o);
        c = __reduce_add_sync(0xFFFFFFFFu, c);
        if (lane == 0) { w_f0[warp] = ssum; atomicAdd(&s_cnt, (unsigned)c); }
        __syncthreads();
        if (tid == 0) {
            float t = 0.0f;
#pragma unroll
            for (int i = 0; i < NW; i++) t += w_f0[i];
            s_sum = t + (float)((int)K - (int)s_cnt) * thr;
        }
        __syncthreads();
        hard = s_sum;
    }

    // ---- per-row results + last-CTA fused finalize ----
    if (tid == 0) {
        g_conf[b] = s_conf + hard;
        g_loc[b]  = s_loc;
        g_npos[b] = npos_b;
        __threadfence();
        unsigned v = atomicAdd(&g_ctr, 1u);
        s_last = (v == (unsigned)(BB - 1));
    }
    __syncthreads();

    if (s_last) {
        __threadfence();
        float l = 0.0f, c = 0.0f; int n = 0;
        if (tid < BB) { l = g_loc[tid]; c = g_conf[tid]; n = g_npos[tid]; }
#pragma unroll
        for (int o = 16; o; o >>= 1) {
            l += __shfl_down_sync(0xFFFFFFFFu, l, o);
            c += __shfl_down_sync(0xFFFFFFFFu, c, o);
        }
        n = __reduce_add_sync(0xFFFFFFFFu, n);
        if (lane == 0) { w_f0[warp] = l; w_f1[warp] = c; w_i0[warp] = n; }
        __syncthreads();
        if (tid == 0) {
            float locsum = 0.0f, confsum = 0.0f; long long np = 0;
#pragma unroll
            for (int i = 0; i < 4; i++) {   // rows live in warps 0-3 only
                locsum += w_f0[i]; confsum += w_f1[i]; np += w_i0[i];
            }
            float npf = (float)np;
            float loc_loss  = (np > 0) ? locsum / (4.0f * fmaxf(npf, 1.0f)) : 0.0f;
            float conf_loss = confsum / (1e-10f + npf);
            float total = conf_loss + loc_loss;
            if (out_size > 0) out[0] = total;
            if (out_size > 1) out[1] = conf_loss;
            if (out_size > 2) out[2] = loc_loss;
            g_ctr = 0u;    // reset for next graph replay
        }
        if (tid < BB && 3 + tid < out_size) out[3 + tid] = (float)g_npos[tid];
        for (int i = 3 + BB + tid; i < out_size; i += TPB) out[i] = 0.0f;
    }
}

extern "C" void kernel_launch(void* const* d_in, const int* in_sizes, int n_in,
                              void* d_out, int out_size) {
    const float* locs   = (const float*)d_in[0];   // (128,8732,4) f32
    const float* scores = (const float*)d_in[1];   // (128,8732,3) f32
    const float* boxes  = (const float*)d_in[2];   // (128,16,4)   f32
    const int*   labels = (const int*)d_in[3];     // (128,16)     i32
    const float* priors = (const float*)d_in[4];   // (8732,4)     f32

    multibox_kernel<<<BB, TPB>>>(locs, scores, boxes, labels, priors,
                                 (float*)d_out, out_size);
}